// round 8
// baseline (speedup 1.0000x reference)
#include <cuda_runtime.h>
#include <cuda.h>
#include <cstdint>

// ---------------- problem constants ----------------
#define N_ROWS  16384
#define D_IN    64
#define D_OUT   32
#define N_PAD   40               // 32 nom | 32:den | 33:alpha | 34..39 zero (5 n8-tiles)
#define TM      64               // rows per CTA (2 CTAs/SM, grid 256)
#define TK      32               // K per pipeline stage
#define STAGES  12
#define K_ITERS (N_ROWS / TK)    // 512

#define STAGE_A_BYTES (TM * TK * 4)              // 8192 (A only; B bypasses smem)
#define SMEM_DYN      (STAGES * STAGE_A_BYTES + 1024)   // 99328

#define NWARPS_C 4               // consumer warps, M=16 each (one per SMSP)
#define NTHREADS (32 * (NWARPS_C + 1))
#define GRID     (N_ROWS / TM)   // 256

// B operand, fragment-packed + LDG-coalesced:
//   float index = kiter*1280 + q*128 + lane*4 + r,  reg j = 4q + r (j in 0..39)
//   j = ((ks*5)+nt)*2 + h  ->  B[k = ks*8+h*4+(lane&3)][n = nt*8+(lane>>2)]
// 512 * 1280 floats = 2.62 MB (L2-resident). Zero-init covers n=34..39 pad.
__device__ float g_Bpk[K_ITERS * 1280];

// ---------------- device helpers ----------------
__device__ __forceinline__ uint32_t smem_u32(const void* p) {
    uint32_t a;
    asm("{ .reg .u64 t; cvta.to.shared.u64 t, %1; cvt.u32.u64 %0, t; }" : "=r"(a) : "l"(p));
    return a;
}
__device__ __forceinline__ float warp_sum(float v) {
    #pragma unroll
    for (int m = 16; m > 0; m >>= 1) v += __shfl_xor_sync(0xffffffffu, v, m);
    return v;
}
__device__ __forceinline__ float artanh_clip(float x) {
    x = fminf(fmaxf(x, -1.0f + 1e-7f), 1.0f - 1e-7f);
    return atanhf(x);
}
__device__ __forceinline__ float tf32_round(float x) {
    uint32_t u;
    asm("cvt.rna.tf32.f32 %0, %1;" : "=r"(u) : "f"(x));
    return __uint_as_float(u);
}
__device__ __forceinline__ uint32_t tf32_bits(float x) {
    uint32_t u;
    asm("cvt.rna.tf32.f32 %0, %1;" : "=r"(u) : "f"(x));
    return u;
}
__device__ __forceinline__ void mbar_init(uint32_t mbar, uint32_t cnt) {
    asm volatile("mbarrier.init.shared.b64 [%0], %1;" :: "r"(mbar), "r"(cnt) : "memory");
}
__device__ __forceinline__ void mbar_expect_tx(uint32_t mbar, uint32_t bytes) {
    asm volatile("mbarrier.arrive.expect_tx.shared.b64 _, [%0], %1;" :: "r"(mbar), "r"(bytes) : "memory");
}
__device__ __forceinline__ void mbar_arrive(uint32_t mbar) {
    asm volatile("mbarrier.arrive.shared.b64 _, [%0];" :: "r"(mbar) : "memory");
}
__device__ __forceinline__ void mbar_wait(uint32_t mbar, uint32_t parity) {
    asm volatile(
        "{\n\t.reg .pred P;\n\t"
        "WL_%=:\n\t"
        "mbarrier.try_wait.parity.shared.b64 P, [%0], %1;\n\t"
        "@!P bra WL_%=;\n\t"
        "}" :: "r"(mbar), "r"(parity) : "memory");
}
__device__ __forceinline__ void tma_load_2d(uint32_t smem_dst, const void* tmap,
                                            int32_t cx, int32_t cy, uint32_t mbar) {
    asm volatile(
        "cp.async.bulk.tensor.2d.shared::cta.global.tile.mbarrier::complete_tx::bytes "
        "[%0], [%1, {%2, %3}], [%4];"
        :: "r"(smem_dst), "l"(tmap), "r"(cx), "r"(cy), "r"(mbar) : "memory");
}
__device__ __forceinline__ float lds32(uint32_t a) {
    float v;
    asm volatile("ld.shared.f32 %0, [%1];" : "=f"(v) : "r"(a));
    return v;
}
__device__ __forceinline__ void mma_tf32(float c[4], uint32_t a0, uint32_t a1, uint32_t a2, uint32_t a3,
                                         uint32_t b0, uint32_t b1) {
    asm volatile(
        "mma.sync.aligned.m16n8k8.row.col.f32.tf32.tf32.f32 "
        "{%0,%1,%2,%3}, {%4,%5,%6,%7}, {%8,%9}, {%0,%1,%2,%3};"
        : "+f"(c[0]), "+f"(c[1]), "+f"(c[2]), "+f"(c[3])
        : "r"(a0), "r"(a1), "r"(a2), "r"(a3), "r"(b0), "r"(b1));
}

// ---------------- kernel 1: build fragment-packed, LDG-coalesced B ----------------
__global__ __launch_bounds__(1024) void prep_kernel(const float* __restrict__ X,
                                                    const float* __restrict__ W) {
    __shared__ float Ws[D_IN * D_OUT];
    const int tid = threadIdx.x;
    for (int t = tid; t < D_IN * D_OUT; t += 1024) Ws[t] = W[t];
    __syncthreads();

    const int w = tid >> 5, lane = tid & 31;
    const int i = blockIdx.x * 32 + w;           // global row (= K index of B)

    const float x0 = X[i * D_IN + lane];
    const float x1 = X[i * D_IN + 32 + lane];
    const float xn = fmaxf(sqrtf(warp_sum(x0 * x0 + x1 * x1)), 1e-15f);

    float mx = 0.0f;
    #pragma unroll
    for (int k = 0; k < 32; ++k) mx = fmaf(__shfl_sync(0xffffffffu, x0, k), Ws[k * 32 + lane], mx);
    #pragma unroll
    for (int k = 0; k < 32; ++k) mx = fmaf(__shfl_sync(0xffffffffu, x1, k), Ws[(k + 32) * 32 + lane], mx);

    const float mxn = fmaxf(sqrtf(warp_sum(mx * mx)), 1e-15f);
    const float t   = tanhf((mxn / xn) * artanh_clip(xn));
    const float xw  = t * (mx / mxn);
    const float x2  = warp_sum(xw * xw);
    const float gamma = 2.0f / fmaxf(1.0f - x2, 1e-15f);

    // scatter into LDG-coalesced fragment layout
    const int ks = (i & 31) >> 3;
    const int h  = (i >> 2) & 1;
    const int il = i & 3;
    const int kiter = i >> 5;
    float* base = g_Bpk + (size_t)kiter * 1280;

    {   // n = lane (0..31): value xw*gamma
        const int j  = ((ks * 5) + (lane >> 3)) * 2 + h;
        const int tl = il | ((lane & 7) << 2);
        base[(j >> 2) * 128 + tl * 4 + (j & 3)] = tf32_round(xw * gamma);
    }
    if (lane < 2) {  // n = 32 (gamma-1), n = 33 (1.0); n=34..39 stay zero
        const float e = (lane == 0) ? (gamma - 1.0f) : 1.0f;
        const int j  = ((ks * 5) + 4) * 2 + h;
        const int tl = il | (lane << 2);
        base[(j >> 2) * 128 + tl * 4 + (j & 3)] = tf32_round(e);
    }
}

// ---------------- kernel 2: A @ Y via TMA(A) + LDG(B) + mma.sync.tf32 ----------------
__global__ __launch_bounds__(NTHREADS, 2) void gemm_kernel(
    const __grid_constant__ CUtensorMap tmA,
    const float* __restrict__ Bpk,
    float* __restrict__ out)
{
    extern __shared__ uint8_t smem_dyn[];
    __shared__ __align__(8) uint64_t full_b[STAGES];
    __shared__ __align__(8) uint64_t empty_b[STAGES];

    const int tid  = threadIdx.x;
    const int wid  = tid >> 5;
    const int lane = tid & 31;

    const uint32_t dyn_base = (smem_u32(smem_dyn) + 1023u) & ~1023u;
    const uint32_t full0  = smem_u32(&full_b[0]);
    const uint32_t empty0 = smem_u32(&empty_b[0]);

    if (tid == 0) {
        for (int s = 0; s < STAGES; ++s) {
            mbar_init(full0 + 8u * s, 1);
            mbar_init(empty0 + 8u * s, NWARPS_C);
        }
    }
    __syncthreads();

    const int row_base = blockIdx.x * TM;

    if (wid == NWARPS_C) {
        // -------- producer: A only --------
        if (lane == 0) {
            uint32_t phase = 1;   // fresh-barrier trick: first empty-wait passes
            int s = 0;
            for (int it = 0; it < K_ITERS; ++it) {
                mbar_wait(empty0 + 8u * s, phase);
                const uint32_t fb = full0 + 8u * s;
                mbar_expect_tx(fb, STAGE_A_BYTES);
                tma_load_2d(dyn_base + (uint32_t)s * STAGE_A_BYTES, &tmA,
                            it * TK, row_base, fb);                 // A box [32 x 64] SW128
                if (++s == STAGES) { s = 0; phase ^= 1; }
            }
        }
        return;
    }

    // -------- consumers: 4 warps (one per SMSP), warp owns rows [wid*16, wid*16+16) --------
    float acc[5][4];
    #pragma unroll
    for (int nt = 0; nt < 5; ++nt)
        #pragma unroll
        for (int q = 0; q < 4; ++q) acc[nt][q] = 0.0f;

    const uint32_t lane2 = lane & 3u, lane4 = lane >> 2;
    const uint32_t sw    = lane4 << 4;                    // SW128 XOR term (row&7 == lane4)
    const uint32_t aoff0 = (uint32_t)(wid * 16 + lane4) * 128u;
    const uint4* __restrict__ bbase = reinterpret_cast<const uint4*>(Bpk) + lane;

    uint32_t phase = 0;
    int s = 0;

    uint4 bq[2][10];    // double-buffered B fragments
    #pragma unroll
    for (int q = 0; q < 10; ++q) bq[0][q] = bbase[q * 32];   // iter 0 B (it*320 + q*32)

    for (int it = 0; it < K_ITERS; ++it) {
        const int cur = it & 1;
        // prefetch next iteration's B before blocking on A
        if (it + 1 < K_ITERS) {
            const uint4* bp = bbase + (size_t)(it + 1) * 320;
            #pragma unroll
            for (int q = 0; q < 10; ++q) bq[cur ^ 1][q] = bp[q * 32];
        }

        mbar_wait(full0 + 8u * s, phase);
        const uint32_t Abase = dyn_base + (uint32_t)s * STAGE_A_BYTES;

        // ---- A: 16 scalar LDS -> staged, then cvt ----
        float afl[4][4];
        {
            const uint32_t r0 = Abase + aoff0;
            #pragma unroll
            for (int ks = 0; ks < 4; ++ks) {
                const uint32_t c0 = (uint32_t)ks * 32u + lane2 * 4u;
                afl[ks][0] = lds32(r0 +          (c0 ^ sw));
                afl[ks][1] = lds32(r0 + 1024u +  (c0 ^ sw));
                afl[ks][2] = lds32(r0 +         ((c0 + 16u) ^ sw));
                afl[ks][3] = lds32(r0 + 1024u + ((c0 + 16u) ^ sw));
            }
        }
        uint32_t au[4][4];
        #pragma unroll
        for (int ks = 0; ks < 4; ++ks)
            #pragma unroll
            for (int q = 0; q < 4; ++q) au[ks][q] = tf32_bits(afl[ks][q]);

        if (lane == 0) mbar_arrive(empty0 + 8u * s);   // regs hold everything

        // ---- mma: br[j] = component (j&3) of bq[cur][j>>2], j = (ks*5+nt)*2 + h ----
        uint32_t br[40];
        #pragma unroll
        for (int q = 0; q < 10; ++q) {
            br[4 * q]     = bq[cur][q].x;
            br[4 * q + 1] = bq[cur][q].y;
            br[4 * q + 2] = bq[cur][q].z;
            br[4 * q + 3] = bq[cur][q].w;
        }
        #pragma unroll
        for (int ks = 0; ks < 4; ++ks)
            #pragma unroll
            for (int nt = 0; nt < 5; ++nt)
                mma_tf32(acc[nt],
                         au[ks][0], au[ks][1], au[ks][2], au[ks][3],
                         br[(ks * 5 + nt) * 2], br[(ks * 5 + nt) * 2 + 1]);

        if (++s == STAGES) { s = 0; phase ^= 1; }
    }

    // -------- epilogue: hyperbolic chain per row-half --------
    #pragma unroll
    for (int h = 0; h < 2; ++h) {
        float v[8];
        #pragma unroll
        for (int nt = 0; nt < 4; ++nt) {
            v[2 * nt]     = acc[nt][2 * h];
            v[2 * nt + 1] = acc[nt][2 * h + 1];
        }
        float den   = __shfl_sync(0xffffffffu, acc[4][2 * h],     lane & ~3);
        float alpha = __shfl_sync(0xffffffffu, acc[4][2 * h + 1], lane & ~3);

        const float sgn = (den >= 0.0f) ? 1.0f : -1.0f;
        den = sgn * fmaxf(fabsf(den), 1e-10f);
        const float inv = 1.0f / den;

        float vn2 = 0.0f;
        #pragma unroll
        for (int c = 0; c < 8; ++c) { v[c] *= inv; vn2 += v[c] * v[c]; }
        vn2 += __shfl_xor_sync(0xffffffffu, vn2, 1);
        vn2 += __shfl_xor_sync(0xffffffffu, vn2, 2);

        const float vn = fmaxf(sqrtf(vn2), 1e-15f);
        const float t1 = tanhf(0.5f * artanh_clip(vn));
        const float rn = fmaxf(t1, 1e-15f);
        const float t2 = tanhf(alpha * artanh_clip(rn));
        const float xs = (t1 / vn) * (t2 / rn);
        const float xn = fmaxf(xs * vn, 1e-15f);
        const float k3 = artanh_clip(xn) / xn;
        const float us = xs * k3;

        float un2 = 0.0f;
        float u[8];
        #pragma unroll
        for (int c = 0; c < 8; ++c) { u[c] = fmaxf(v[c] * us, 0.0f); un2 += u[c] * u[c]; }
        un2 += __shfl_xor_sync(0xffffffffu, un2, 1);
        un2 += __shfl_xor_sync(0xffffffffu, un2, 2);

        const float un = fmaxf(sqrtf(un2), 1e-15f);
        const float k4 = tanhf(un) / un;

        const int row = row_base + wid * 16 + h * 8 + (lane >> 2);
        float* op = out + (size_t)row * D_OUT + 2 * (lane & 3);
        #pragma unroll
        for (int nt = 0; nt < 4; ++nt)
            *reinterpret_cast<float2*>(op + nt * 8) =
                make_float2(u[2 * nt] * k4, u[2 * nt + 1] * k4);
    }
}

// ---------------- host ----------------
typedef CUresult (CUDAAPI *PFN_cuTensorMapEncodeTiled_t)(
    CUtensorMap*, CUtensorMapDataType, cuuint32_t, void*,
    const cuuint64_t*, const cuuint64_t*, const cuuint32_t*, const cuuint32_t*,
    CUtensorMapInterleave, CUtensorMapSwizzle, CUtensorMapL2promotion, CUtensorMapFloatOOBfill);

extern "C" void kernel_launch(void* const* d_in, const int* in_sizes, int n_in,
                              void* d_out, int out_size) {
    const float* X = nullptr; const float* A = nullptr; const float* W = nullptr;
    for (int i = 0; i < n_in; ++i) {
        if (in_sizes[i] == N_ROWS * D_IN)     X = (const float*)d_in[i];
        else if (in_sizes[i] == D_IN * D_OUT) W = (const float*)d_in[i];
        else                                  A = (const float*)d_in[i];   // 16384^2
    }
    float* out = (float*)d_out;

    void* b_ptr = nullptr;
    cudaGetSymbolAddress(&b_ptr, g_Bpk);

    PFN_cuTensorMapEncodeTiled_t encode = nullptr;
    cudaDriverEntryPointQueryResult qr;
    cudaGetDriverEntryPointByVersion("cuTensorMapEncodeTiled", (void**)&encode,
                                     12000, cudaEnableDefault, &qr);

    CUtensorMap tmA;
    {   // A: [16384 x 16384] fp32, box [K=32, M=64], SW128
        cuuint64_t dims[2]    = {N_ROWS, N_ROWS};
        cuuint64_t strides[1] = {(cuuint64_t)N_ROWS * 4};
        cuuint32_t box[2]     = {TK, TM};
        cuuint32_t estr[2]    = {1, 1};
        encode(&tmA, CU_TENSOR_MAP_DATA_TYPE_FLOAT32, 2, (void*)A,
               dims, strides, box, estr,
               CU_TENSOR_MAP_INTERLEAVE_NONE, CU_TENSOR_MAP_SWIZZLE_128B,
               CU_TENSOR_MAP_L2_PROMOTION_L2_128B, CU_TENSOR_MAP_FLOAT_OOB_FILL_NONE);
    }

    prep_kernel<<<N_ROWS / 32, 1024>>>(X, W);

    cudaFuncSetAttribute(gemm_kernel, cudaFuncAttributeMaxDynamicSharedMemorySize, SMEM_DYN);
    gemm_kernel<<<GRID, NTHREADS, SMEM_DYN>>>(tmA, (const float*)b_ptr, out);
}

// round 9
// speedup vs baseline: 2.3909x; 2.3909x over previous
#include <cuda_runtime.h>
#include <cuda.h>
#include <cstdint>

// ---------------- problem constants ----------------
#define N_ROWS  16384
#define D_IN    64
#define D_OUT   32
#define N_PAD   40               // 32 nom | 32:den | 33:alpha | 34..39 zero (5 n8-tiles)
#define TM      64               // rows per CTA (2 CTAs/SM, grid 256)
#define TK      32               // K per pipeline stage
#define STAGES  12
#define K_ITERS (N_ROWS / TK)    // 512

#define STAGE_A_BYTES (TM * TK * 4)              // 8192 (A only; B bypasses smem)
#define SMEM_DYN      (STAGES * STAGE_A_BYTES + 1024)   // 99328

#define NWARPS_C 4               // consumer warps, M=16 each (one per SMSP)
#define NTHREADS (32 * (NWARPS_C + 1))
#define GRID     (N_ROWS / TM)   // 256

// B operand, fragment-packed + LDG-coalesced:
//   float index = kiter*1280 + q*128 + lane*4 + r,  reg j = 4q + r (j in 0..39)
//   j = ((ks*5)+nt)*2 + h  ->  B[k = ks*8+h*4+(lane&3)][n = nt*8+(lane>>2)]
// 512 * 1280 floats = 2.62 MB (L2-resident). Zero-init covers n=34..39 pad.
__device__ float g_Bpk[K_ITERS * 1280];

// ---------------- device helpers ----------------
__device__ __forceinline__ uint32_t smem_u32(const void* p) {
    uint32_t a;
    asm("{ .reg .u64 t; cvta.to.shared.u64 t, %1; cvt.u32.u64 %0, t; }" : "=r"(a) : "l"(p));
    return a;
}
__device__ __forceinline__ float warp_sum(float v) {
    #pragma unroll
    for (int m = 16; m > 0; m >>= 1) v += __shfl_xor_sync(0xffffffffu, v, m);
    return v;
}
__device__ __forceinline__ float artanh_clip(float x) {
    x = fminf(fmaxf(x, -1.0f + 1e-7f), 1.0f - 1e-7f);
    return atanhf(x);
}
__device__ __forceinline__ float tf32_round(float x) {
    uint32_t u;
    asm("cvt.rna.tf32.f32 %0, %1;" : "=r"(u) : "f"(x));
    return __uint_as_float(u);
}
__device__ __forceinline__ uint32_t tf32_bits(float x) {
    uint32_t u;
    asm("cvt.rna.tf32.f32 %0, %1;" : "=r"(u) : "f"(x));
    return u;
}
__device__ __forceinline__ void mbar_init(uint32_t mbar, uint32_t cnt) {
    asm volatile("mbarrier.init.shared.b64 [%0], %1;" :: "r"(mbar), "r"(cnt) : "memory");
}
__device__ __forceinline__ void mbar_expect_tx(uint32_t mbar, uint32_t bytes) {
    asm volatile("mbarrier.arrive.expect_tx.shared.b64 _, [%0], %1;" :: "r"(mbar), "r"(bytes) : "memory");
}
__device__ __forceinline__ void mbar_arrive(uint32_t mbar) {
    asm volatile("mbarrier.arrive.shared.b64 _, [%0];" :: "r"(mbar) : "memory");
}
__device__ __forceinline__ void mbar_wait(uint32_t mbar, uint32_t parity) {
    asm volatile(
        "{\n\t.reg .pred P;\n\t"
        "WL_%=:\n\t"
        "mbarrier.try_wait.parity.shared.b64 P, [%0], %1;\n\t"
        "@!P bra WL_%=;\n\t"
        "}" :: "r"(mbar), "r"(parity) : "memory");
}
__device__ __forceinline__ void tma_load_2d(uint32_t smem_dst, const void* tmap,
                                            int32_t cx, int32_t cy, uint32_t mbar) {
    asm volatile(
        "cp.async.bulk.tensor.2d.shared::cta.global.tile.mbarrier::complete_tx::bytes "
        "[%0], [%1, {%2, %3}], [%4];"
        :: "r"(smem_dst), "l"(tmap), "r"(cx), "r"(cy), "r"(mbar) : "memory");
}
__device__ __forceinline__ float lds32(uint32_t a) {
    float v;
    asm volatile("ld.shared.f32 %0, [%1];" : "=f"(v) : "r"(a));
    return v;
}
__device__ __forceinline__ void mma_tf32(float c[4], uint32_t a0, uint32_t a1, uint32_t a2, uint32_t a3,
                                         uint32_t b0, uint32_t b1) {
    asm volatile(
        "mma.sync.aligned.m16n8k8.row.col.f32.tf32.tf32.f32 "
        "{%0,%1,%2,%3}, {%4,%5,%6,%7}, {%8,%9}, {%0,%1,%2,%3};"
        : "+f"(c[0]), "+f"(c[1]), "+f"(c[2]), "+f"(c[3])
        : "r"(a0), "r"(a1), "r"(a2), "r"(a3), "r"(b0), "r"(b1));
}

// ---------------- kernel 1: build fragment-packed, LDG-coalesced B ----------------
__global__ __launch_bounds__(1024) void prep_kernel(const float* __restrict__ X,
                                                    const float* __restrict__ W) {
    __shared__ float Ws[D_IN * D_OUT];
    const int tid = threadIdx.x;
    for (int t = tid; t < D_IN * D_OUT; t += 1024) Ws[t] = W[t];
    __syncthreads();

    const int w = tid >> 5, lane = tid & 31;
    const int i = blockIdx.x * 32 + w;           // global row (= K index of B)

    const float x0 = X[i * D_IN + lane];
    const float x1 = X[i * D_IN + 32 + lane];
    const float xn = fmaxf(sqrtf(warp_sum(x0 * x0 + x1 * x1)), 1e-15f);

    float mx = 0.0f;
    #pragma unroll
    for (int k = 0; k < 32; ++k) mx = fmaf(__shfl_sync(0xffffffffu, x0, k), Ws[k * 32 + lane], mx);
    #pragma unroll
    for (int k = 0; k < 32; ++k) mx = fmaf(__shfl_sync(0xffffffffu, x1, k), Ws[(k + 32) * 32 + lane], mx);

    const float mxn = fmaxf(sqrtf(warp_sum(mx * mx)), 1e-15f);
    const float t   = tanhf((mxn / xn) * artanh_clip(xn));
    const float xw  = t * (mx / mxn);
    const float x2  = warp_sum(xw * xw);
    const float gamma = 2.0f / fmaxf(1.0f - x2, 1e-15f);

    // scatter into LDG-coalesced fragment layout
    const int ks = (i & 31) >> 3;
    const int h  = (i >> 2) & 1;
    const int il = i & 3;
    const int kiter = i >> 5;
    float* base = g_Bpk + (size_t)kiter * 1280;

    {   // n = lane (0..31): value xw*gamma
        const int j  = ((ks * 5) + (lane >> 3)) * 2 + h;
        const int tl = il | ((lane & 7) << 2);
        base[(j >> 2) * 128 + tl * 4 + (j & 3)] = tf32_round(xw * gamma);
    }
    if (lane < 2) {  // n = 32 (gamma-1), n = 33 (1.0); n=34..39 stay zero
        const float e = (lane == 0) ? (gamma - 1.0f) : 1.0f;
        const int j  = ((ks * 5) + 4) * 2 + h;
        const int tl = il | (lane << 2);
        base[(j >> 2) * 128 + tl * 4 + (j & 3)] = tf32_round(e);
    }
}

// ---------------- kernel 2: A @ Y via TMA(A) + LDG(B) + mma.sync.tf32 ----------------
__global__ __launch_bounds__(NTHREADS, 2) void gemm_kernel(
    const __grid_constant__ CUtensorMap tmA,
    const float* __restrict__ Bpk,
    float* __restrict__ out)
{
    extern __shared__ uint8_t smem_dyn[];
    __shared__ __align__(8) uint64_t full_b[STAGES];
    __shared__ __align__(8) uint64_t empty_b[STAGES];

    const int tid  = threadIdx.x;
    const int wid  = tid >> 5;
    const int lane = tid & 31;

    const uint32_t dyn_base = (smem_u32(smem_dyn) + 1023u) & ~1023u;
    const uint32_t full0  = smem_u32(&full_b[0]);
    const uint32_t empty0 = smem_u32(&empty_b[0]);

    if (tid == 0) {
        for (int s = 0; s < STAGES; ++s) {
            mbar_init(full0 + 8u * s, 1);
            mbar_init(empty0 + 8u * s, NWARPS_C);
        }
    }
    __syncthreads();

    const int row_base = blockIdx.x * TM;

    if (wid == NWARPS_C) {
        // -------- producer: A only --------
        if (lane == 0) {
            uint32_t phase = 1;   // fresh-barrier trick: first empty-wait passes
            int s = 0;
            for (int it = 0; it < K_ITERS; ++it) {
                mbar_wait(empty0 + 8u * s, phase);
                const uint32_t fb = full0 + 8u * s;
                mbar_expect_tx(fb, STAGE_A_BYTES);
                tma_load_2d(dyn_base + (uint32_t)s * STAGE_A_BYTES, &tmA,
                            it * TK, row_base, fb);                 // A box [32 x 64] SW128
                if (++s == STAGES) { s = 0; phase ^= 1; }
            }
        }
        return;
    }

    // -------- consumers: 4 warps (one per SMSP), warp owns rows [wid*16, wid*16+16) --------
    float acc[5][4];
    #pragma unroll
    for (int nt = 0; nt < 5; ++nt)
        #pragma unroll
        for (int q = 0; q < 4; ++q) acc[nt][q] = 0.0f;

    const uint32_t lane2 = lane & 3u, lane4 = lane >> 2;
    const uint32_t sw    = lane4 << 4;                    // SW128 XOR term (row&7 == lane4)
    const uint32_t aoff0 = (uint32_t)(wid * 16 + lane4) * 128u;
    const uint4* __restrict__ bbase = reinterpret_cast<const uint4*>(Bpk) + lane;

    uint32_t phase = 0;
    int s = 0;

    // Two statically-named B fragment buffers -> all register-resident
    // (R8 bug: runtime-indexed bq[2][10] spilled to local memory).
    uint4 bqA[10], bqB[10];
    #pragma unroll
    for (int q = 0; q < 10; ++q) bqA[q] = bbase[q * 32];   // iter 0 B

    #define CONSUME_HALF(BQ, IT_NEXT, BQN)                                         \
    {                                                                              \
        /* prefetch next iteration's B before blocking on A */                     \
        {                                                                          \
            const int itn = (IT_NEXT) < K_ITERS ? (IT_NEXT) : (K_ITERS - 1);       \
            const uint4* bp = bbase + (size_t)itn * 320;                           \
            _Pragma("unroll")                                                      \
            for (int q = 0; q < 10; ++q) (BQN)[q] = bp[q * 32];                    \
        }                                                                          \
        mbar_wait(full0 + 8u * s, phase);                                          \
        const uint32_t Abase = dyn_base + (uint32_t)s * STAGE_A_BYTES;             \
        float afl[4][4];                                                           \
        {                                                                          \
            const uint32_t r0 = Abase + aoff0;                                     \
            _Pragma("unroll")                                                      \
            for (int ks = 0; ks < 4; ++ks) {                                       \
                const uint32_t c0 = (uint32_t)ks * 32u + lane2 * 4u;               \
                afl[ks][0] = lds32(r0 +          (c0 ^ sw));                       \
                afl[ks][1] = lds32(r0 + 1024u +  (c0 ^ sw));                       \
                afl[ks][2] = lds32(r0 +         ((c0 + 16u) ^ sw));                \
                afl[ks][3] = lds32(r0 + 1024u + ((c0 + 16u) ^ sw));                \
            }                                                                      \
        }                                                                          \
        uint32_t au[4][4];                                                         \
        _Pragma("unroll")                                                          \
        for (int ks = 0; ks < 4; ++ks)                                             \
            _Pragma("unroll")                                                      \
            for (int q = 0; q < 4; ++q) au[ks][q] = tf32_bits(afl[ks][q]);         \
        if (lane == 0) mbar_arrive(empty0 + 8u * s);                               \
        _Pragma("unroll")                                                          \
        for (int ks = 0; ks < 4; ++ks)                                             \
            _Pragma("unroll")                                                      \
            for (int nt = 0; nt < 5; ++nt) {                                       \
                const int j0 = (ks * 5 + nt) * 2;                                  \
                const uint32_t b0 = (&(BQ)[j0 >> 2].x)[j0 & 3];                    \
                const uint32_t b1 = (&(BQ)[(j0 + 1) >> 2].x)[(j0 + 1) & 3];        \
                mma_tf32(acc[nt], au[ks][0], au[ks][1], au[ks][2], au[ks][3],      \
                         b0, b1);                                                  \
            }                                                                      \
        if (++s == STAGES) { s = 0; phase ^= 1; }                                  \
    }

    for (int it = 0; it < K_ITERS; it += 2) {
        CONSUME_HALF(bqA, it + 1, bqB)     // consume even iter, prefetch odd
        CONSUME_HALF(bqB, it + 2, bqA)     // consume odd iter,  prefetch next even
    }
    #undef CONSUME_HALF

    // -------- epilogue: hyperbolic chain per row-half --------
    #pragma unroll
    for (int h = 0; h < 2; ++h) {
        float v[8];
        #pragma unroll
        for (int nt = 0; nt < 4; ++nt) {
            v[2 * nt]     = acc[nt][2 * h];
            v[2 * nt + 1] = acc[nt][2 * h + 1];
        }
        float den   = __shfl_sync(0xffffffffu, acc[4][2 * h],     lane & ~3);
        float alpha = __shfl_sync(0xffffffffu, acc[4][2 * h + 1], lane & ~3);

        const float sgn = (den >= 0.0f) ? 1.0f : -1.0f;
        den = sgn * fmaxf(fabsf(den), 1e-10f);
        const float inv = 1.0f / den;

        float vn2 = 0.0f;
        #pragma unroll
        for (int c = 0; c < 8; ++c) { v[c] *= inv; vn2 += v[c] * v[c]; }
        vn2 += __shfl_xor_sync(0xffffffffu, vn2, 1);
        vn2 += __shfl_xor_sync(0xffffffffu, vn2, 2);

        const float vn = fmaxf(sqrtf(vn2), 1e-15f);
        const float t1 = tanhf(0.5f * artanh_clip(vn));
        const float rn = fmaxf(t1, 1e-15f);
        const float t2 = tanhf(alpha * artanh_clip(rn));
        const float xs = (t1 / vn) * (t2 / rn);
        const float xn = fmaxf(xs * vn, 1e-15f);
        const float k3 = artanh_clip(xn) / xn;
        const float us = xs * k3;

        float un2 = 0.0f;
        float u[8];
        #pragma unroll
        for (int c = 0; c < 8; ++c) { u[c] = fmaxf(v[c] * us, 0.0f); un2 += u[c] * u[c]; }
        un2 += __shfl_xor_sync(0xffffffffu, un2, 1);
        un2 += __shfl_xor_sync(0xffffffffu, un2, 2);

        const float un = fmaxf(sqrtf(un2), 1e-15f);
        const float k4 = tanhf(un) / un;

        const int row = row_base + wid * 16 + h * 8 + (lane >> 2);
        float* op = out + (size_t)row * D_OUT + 2 * (lane & 3);
        #pragma unroll
        for (int nt = 0; nt < 4; ++nt)
            *reinterpret_cast<float2*>(op + nt * 8) =
                make_float2(u[2 * nt] * k4, u[2 * nt + 1] * k4);
    }
}

// ---------------- host ----------------
typedef CUresult (CUDAAPI *PFN_cuTensorMapEncodeTiled_t)(
    CUtensorMap*, CUtensorMapDataType, cuuint32_t, void*,
    const cuuint64_t*, const cuuint64_t*, const cuuint32_t*, const cuuint32_t*,
    CUtensorMapInterleave, CUtensorMapSwizzle, CUtensorMapL2promotion, CUtensorMapFloatOOBfill);

extern "C" void kernel_launch(void* const* d_in, const int* in_sizes, int n_in,
                              void* d_out, int out_size) {
    const float* X = nullptr; const float* A = nullptr; const float* W = nullptr;
    for (int i = 0; i < n_in; ++i) {
        if (in_sizes[i] == N_ROWS * D_IN)     X = (const float*)d_in[i];
        else if (in_sizes[i] == D_IN * D_OUT) W = (const float*)d_in[i];
        else                                  A = (const float*)d_in[i];   // 16384^2
    }
    float* out = (float*)d_out;

    void* b_ptr = nullptr;
    cudaGetSymbolAddress(&b_ptr, g_Bpk);

    PFN_cuTensorMapEncodeTiled_t encode = nullptr;
    cudaDriverEntryPointQueryResult qr;
    cudaGetDriverEntryPointByVersion("cuTensorMapEncodeTiled", (void**)&encode,
                                     12000, cudaEnableDefault, &qr);

    CUtensorMap tmA;
    {   // A: [16384 x 16384] fp32, box [K=32, M=64], SW128
        cuuint64_t dims[2]    = {N_ROWS, N_ROWS};
        cuuint64_t strides[1] = {(cuuint64_t)N_ROWS * 4};
        cuuint32_t box[2]     = {TK, TM};
        cuuint32_t estr[2]    = {1, 1};
        encode(&tmA, CU_TENSOR_MAP_DATA_TYPE_FLOAT32, 2, (void*)A,
               dims, strides, box, estr,
               CU_TENSOR_MAP_INTERLEAVE_NONE, CU_TENSOR_MAP_SWIZZLE_128B,
               CU_TENSOR_MAP_L2_PROMOTION_L2_128B, CU_TENSOR_MAP_FLOAT_OOB_FILL_NONE);
    }

    prep_kernel<<<N_ROWS / 32, 1024>>>(X, W);

    cudaFuncSetAttribute(gemm_kernel, cudaFuncAttributeMaxDynamicSharedMemorySize, SMEM_DYN);
    gemm_kernel<<<GRID, NTHREADS, SMEM_DYN>>>(tmA, (const float*)b_ptr, out);
}

// round 10
// speedup vs baseline: 2.8594x; 1.1960x over previous
#include <cuda_runtime.h>
#include <cuda.h>
#include <cstdint>

// ---------------- problem constants ----------------
#define N_ROWS  16384
#define D_IN    64
#define D_OUT   32
#define TM      64               // rows per CTA (2 CTAs/SM, grid 256)
#define TK      32               // K per pipeline stage
#define STAGES  6
#define K_ITERS (N_ROWS / TK)    // 512

#define STAGE_A_BYTES (TM * TK * 4)          // 8192
#define STAGE_B_BYTES (4 * 32 * 12 * 4)      // 6144  ([ks][lane][12 floats])
#define STAGE_BYTES   (STAGE_A_BYTES + STAGE_B_BYTES)   // 14336
#define SMEM_DYN      (STAGES * STAGE_BYTES + 1024)     // 87040

#define NWARPS_C 4               // consumer warps; warp w owns K-slice ks=w of ALL 64 rows
#define NTHREADS (32 * (NWARPS_C + 1))
#define GRID     (N_ROWS / TM)   // 256

// B operand, fragment-packed for K-split: [kiter][ks][lane][12 floats] (j' 0..9 used)
//   j' = nt*2 + h  ->  B[k = ks*8 + h*4 + (lane&3)][n = nt*8 + (lane>>2)]
// 512 * 1536 floats = 3.1 MB (L2-resident).
__device__ float g_Bpk[K_ITERS * 1536];

// ---------------- device helpers ----------------
__device__ __forceinline__ uint32_t smem_u32(const void* p) {
    uint32_t a;
    asm("{ .reg .u64 t; cvta.to.shared.u64 t, %1; cvt.u32.u64 %0, t; }" : "=r"(a) : "l"(p));
    return a;
}
__device__ __forceinline__ float warp_sum(float v) {
    #pragma unroll
    for (int m = 16; m > 0; m >>= 1) v += __shfl_xor_sync(0xffffffffu, v, m);
    return v;
}
__device__ __forceinline__ float artanh_clip(float x) {
    x = fminf(fmaxf(x, -1.0f + 1e-7f), 1.0f - 1e-7f);
    return atanhf(x);
}
__device__ __forceinline__ float tf32_round(float x) {
    uint32_t u;
    asm("cvt.rna.tf32.f32 %0, %1;" : "=r"(u) : "f"(x));
    return __uint_as_float(u);
}
__device__ __forceinline__ uint32_t tf32_bits(float x) {
    uint32_t u;
    asm("cvt.rna.tf32.f32 %0, %1;" : "=r"(u) : "f"(x));
    return u;
}
__device__ __forceinline__ void mbar_init(uint32_t mbar, uint32_t cnt) {
    asm volatile("mbarrier.init.shared.b64 [%0], %1;" :: "r"(mbar), "r"(cnt) : "memory");
}
__device__ __forceinline__ void mbar_expect_tx(uint32_t mbar, uint32_t bytes) {
    asm volatile("mbarrier.arrive.expect_tx.shared.b64 _, [%0], %1;" :: "r"(mbar), "r"(bytes) : "memory");
}
__device__ __forceinline__ void mbar_arrive(uint32_t mbar) {
    asm volatile("mbarrier.arrive.shared.b64 _, [%0];" :: "r"(mbar) : "memory");
}
__device__ __forceinline__ void mbar_wait(uint32_t mbar, uint32_t parity) {
    asm volatile(
        "{\n\t.reg .pred P;\n\t"
        "WL_%=:\n\t"
        "mbarrier.try_wait.parity.shared.b64 P, [%0], %1;\n\t"
        "@!P bra WL_%=;\n\t"
        "}" :: "r"(mbar), "r"(parity) : "memory");
}
__device__ __forceinline__ void tma_load_2d(uint32_t smem_dst, const void* tmap,
                                            int32_t cx, int32_t cy, uint32_t mbar) {
    asm volatile(
        "cp.async.bulk.tensor.2d.shared::cta.global.tile.mbarrier::complete_tx::bytes "
        "[%0], [%1, {%2, %3}], [%4];"
        :: "r"(smem_dst), "l"(tmap), "r"(cx), "r"(cy), "r"(mbar) : "memory");
}
__device__ __forceinline__ void bulk_load(uint32_t smem_dst, const void* gsrc,
                                          uint32_t bytes, uint32_t mbar) {
    asm volatile(
        "cp.async.bulk.shared::cta.global.mbarrier::complete_tx::bytes [%0], [%1], %2, [%3];"
        :: "r"(smem_dst), "l"(gsrc), "r"(bytes), "r"(mbar) : "memory");
}
__device__ __forceinline__ float lds32(uint32_t a) {
    float v;
    asm volatile("ld.shared.f32 %0, [%1];" : "=f"(v) : "r"(a));
    return v;
}
__device__ __forceinline__ void lds128(uint32_t a, uint32_t r[4]) {
    asm volatile("ld.shared.v4.u32 {%0,%1,%2,%3}, [%4];"
                 : "=r"(r[0]), "=r"(r[1]), "=r"(r[2]), "=r"(r[3]) : "r"(a));
}
__device__ __forceinline__ void lds128f(uint32_t a, float r[4]) {
    asm volatile("ld.shared.v4.f32 {%0,%1,%2,%3}, [%4];"
                 : "=f"(r[0]), "=f"(r[1]), "=f"(r[2]), "=f"(r[3]) : "r"(a));
}
__device__ __forceinline__ void sts128f(uint32_t a, const float r[4]) {
    asm volatile("st.shared.v4.f32 [%0], {%1,%2,%3,%4};"
                 :: "r"(a), "f"(r[0]), "f"(r[1]), "f"(r[2]), "f"(r[3]) : "memory");
}
__device__ __forceinline__ void mma_tf32(float c[4], uint32_t a0, uint32_t a1, uint32_t a2, uint32_t a3,
                                         uint32_t b0, uint32_t b1) {
    asm volatile(
        "mma.sync.aligned.m16n8k8.row.col.f32.tf32.tf32.f32 "
        "{%0,%1,%2,%3}, {%4,%5,%6,%7}, {%8,%9}, {%0,%1,%2,%3};"
        : "+f"(c[0]), "+f"(c[1]), "+f"(c[2]), "+f"(c[3])
        : "r"(a0), "r"(a1), "r"(a2), "r"(a3), "r"(b0), "r"(b1));
}

// ---------------- kernel 1: build fragment-packed B (K-split layout) ----------------
__global__ __launch_bounds__(1024) void prep_kernel(const float* __restrict__ X,
                                                    const float* __restrict__ W) {
    __shared__ float Ws[D_IN * D_OUT];
    const int tid = threadIdx.x;
    for (int t = tid; t < D_IN * D_OUT; t += 1024) Ws[t] = W[t];
    __syncthreads();

    const int w = tid >> 5, lane = tid & 31;
    const int i = blockIdx.x * 32 + w;           // global row (= K index of B)

    const float x0 = X[i * D_IN + lane];
    const float x1 = X[i * D_IN + 32 + lane];
    const float xn = fmaxf(sqrtf(warp_sum(x0 * x0 + x1 * x1)), 1e-15f);

    float mx = 0.0f;
    #pragma unroll
    for (int k = 0; k < 32; ++k) mx = fmaf(__shfl_sync(0xffffffffu, x0, k), Ws[k * 32 + lane], mx);
    #pragma unroll
    for (int k = 0; k < 32; ++k) mx = fmaf(__shfl_sync(0xffffffffu, x1, k), Ws[(k + 32) * 32 + lane], mx);

    const float mxn = fmaxf(sqrtf(warp_sum(mx * mx)), 1e-15f);
    const float t   = tanhf((mxn / xn) * artanh_clip(xn));
    const float xw  = t * (mx / mxn);
    const float x2  = warp_sum(xw * xw);
    const float gamma = 2.0f / fmaxf(1.0f - x2, 1e-15f);

    // scatter into K-split fragment layout: [kiter][ks][lane][12]
    const int ks = (i & 31) >> 3;
    const int h  = (i >> 2) & 1;
    const int il = i & 3;
    const int kiter = i >> 5;
    float* base = g_Bpk + (size_t)kiter * 1536 + ks * 384;

    {   // n = lane (0..31): value xw*gamma
        const int tl = il | ((lane & 7) << 2);
        const int jp = (lane >> 3) * 2 + h;
        base[tl * 12 + jp] = tf32_round(xw * gamma);
    }
    if (lane < 2) {  // n = 32 (gamma-1), n = 33 (1.0)
        const float e = (lane == 0) ? (gamma - 1.0f) : 1.0f;
        const int tl = il | (lane << 2);
        base[tl * 12 + 8 + h] = tf32_round(e);
    }
}

// ---------------- kernel 2: A @ Y via TMA(A)+bulk(B)+mma.sync.tf32, K-split consumers ----------------
__global__ __launch_bounds__(NTHREADS, 2) void gemm_kernel(
    const __grid_constant__ CUtensorMap tmA,
    const float* __restrict__ Bpk,
    float* __restrict__ out)
{
    extern __shared__ uint8_t smem_dyn[];
    __shared__ __align__(8) uint64_t full_b[STAGES];
    __shared__ __align__(8) uint64_t empty_b[STAGES];

    const int tid  = threadIdx.x;
    const int wid  = tid >> 5;
    const int lane = tid & 31;

    const uint32_t dyn_base = (smem_u32(smem_dyn) + 1023u) & ~1023u;
    const uint32_t full0  = smem_u32(&full_b[0]);
    const uint32_t empty0 = smem_u32(&empty_b[0]);

    if (tid == 0) {
        for (int s = 0; s < STAGES; ++s) {
            mbar_init(full0 + 8u * s, 1);
            mbar_init(empty0 + 8u * s, NWARPS_C);
        }
    }
    __syncthreads();

    const int row_base = blockIdx.x * TM;

    if (wid == NWARPS_C) {
        // -------- producer --------
        if (lane == 0) {
            uint32_t phase = 1;   // fresh-barrier trick: first empty-wait passes
            int s = 0;
            for (int it = 0; it < K_ITERS; ++it) {
                mbar_wait(empty0 + 8u * s, phase);
                const uint32_t fb = full0 + 8u * s;
                mbar_expect_tx(fb, STAGE_BYTES);
                const uint32_t a_dst = dyn_base + (uint32_t)s * STAGE_BYTES;
                tma_load_2d(a_dst, &tmA, it * TK, row_base, fb);    // A box [32 x 64] SW128
                bulk_load(a_dst + STAGE_A_BYTES,
                          Bpk + (size_t)it * 1536, STAGE_B_BYTES, fb);
                if (++s == STAGES) { s = 0; phase ^= 1; }
            }
        }
        return;
    }

    // -------- consumers: warp w owns K-slice ks=w of all 64 rows --------
    float acc[4][5][4];   // [m-tile][n-tile][frag]
    #pragma unroll
    for (int mt = 0; mt < 4; ++mt)
        #pragma unroll
        for (int nt = 0; nt < 5; ++nt)
            #pragma unroll
            for (int q = 0; q < 4; ++q) acc[mt][nt][q] = 0.0f;

    const uint32_t lane2 = lane & 3u, lane4 = lane >> 2;
    const uint32_t sw    = lane4 << 4;                          // SW128 XOR (row&7 == lane4)
    const uint32_t c0    = (uint32_t)wid * 32u + lane2 * 4u;    // K-slice byte col
    const uint32_t boff  = STAGE_A_BYTES + (uint32_t)wid * 1536u + lane * 48u;

    uint32_t phase = 0;
    int s = 0;
    for (int it = 0; it < K_ITERS; ++it) {
        mbar_wait(full0 + 8u * s, phase);
        const uint32_t Abase = dyn_base + (uint32_t)s * STAGE_BYTES;

        // ---- B: 3x LDS.128 (48B lane stride -> conflict-free) ----
        uint32_t b0[4], b1[4], b2[4];
        {
            const uint32_t bb = Abase + boff;
            lds128(bb, b0); lds128(bb + 16u, b1); lds128(bb + 32u, b2);
        }
        // ---- A: 16 scalar LDS (4 m-tiles x 4 frags), then cvt ----
        float afl[4][4];
        #pragma unroll
        for (int mt = 0; mt < 4; ++mt) {
            const uint32_t r0 = Abase + (uint32_t)mt * 2048u + lane4 * 128u;
            afl[mt][0] = lds32(r0 +          (c0 ^ sw));
            afl[mt][1] = lds32(r0 + 1024u +  (c0 ^ sw));
            afl[mt][2] = lds32(r0 +         ((c0 + 16u) ^ sw));
            afl[mt][3] = lds32(r0 + 1024u + ((c0 + 16u) ^ sw));
        }
        uint32_t au[4][4];
        #pragma unroll
        for (int mt = 0; mt < 4; ++mt)
            #pragma unroll
            for (int q = 0; q < 4; ++q) au[mt][q] = tf32_bits(afl[mt][q]);

        if (lane == 0) mbar_arrive(empty0 + 8u * s);   // regs hold everything

        #pragma unroll
        for (int mt = 0; mt < 4; ++mt) {
            mma_tf32(acc[mt][0], au[mt][0], au[mt][1], au[mt][2], au[mt][3], b0[0], b0[1]);
            mma_tf32(acc[mt][1], au[mt][0], au[mt][1], au[mt][2], au[mt][3], b0[2], b0[3]);
            mma_tf32(acc[mt][2], au[mt][0], au[mt][1], au[mt][2], au[mt][3], b1[0], b1[1]);
            mma_tf32(acc[mt][3], au[mt][0], au[mt][1], au[mt][2], au[mt][3], b1[2], b1[3]);
            mma_tf32(acc[mt][4], au[mt][0], au[mt][1], au[mt][2], au[mt][3], b2[0], b2[1]);
        }

        if (++s == STAGES) { s = 0; phase ^= 1; }
    }

    // -------- cross-warp K-reduction via smem (pipeline region reused) --------
    asm volatile("bar.sync 1, 128;" ::: "memory");   // all consumers done with stages
    {
        const uint32_t woff = dyn_base + (uint32_t)wid * 10240u + lane * 16u;
        #pragma unroll
        for (int mt = 0; mt < 4; ++mt)
            #pragma unroll
            for (int nt = 0; nt < 5; ++nt)
                sts128f(woff + (uint32_t)(mt * 5 + nt) * 512u, acc[mt][nt]);
    }
    asm volatile("bar.sync 1, 128;" ::: "memory");

    float vsum[5][4];
    #pragma unroll
    for (int nt = 0; nt < 5; ++nt)
        #pragma unroll
        for (int q = 0; q < 4; ++q) vsum[nt][q] = 0.0f;
    #pragma unroll
    for (int sw_ = 0; sw_ < 4; ++sw_) {
        const uint32_t base = dyn_base + (uint32_t)sw_ * 10240u + lane * 16u;
        #pragma unroll
        for (int nt = 0; nt < 5; ++nt) {
            float tmp[4];
            lds128f(base + (uint32_t)(wid * 5 + nt) * 512u, tmp);
            #pragma unroll
            for (int q = 0; q < 4; ++q) vsum[nt][q] += tmp[q];
        }
    }

    // -------- epilogue: hyperbolic chain per row-half (warp owns rows wid*16..+15) --------
    #pragma unroll
    for (int h = 0; h < 2; ++h) {
        float v[8];
        #pragma unroll
        for (int nt = 0; nt < 4; ++nt) {
            v[2 * nt]     = vsum[nt][2 * h];
            v[2 * nt + 1] = vsum[nt][2 * h + 1];
        }
        float den   = __shfl_sync(0xffffffffu, vsum[4][2 * h],     lane & ~3);
        float alpha = __shfl_sync(0xffffffffu, vsum[4][2 * h + 1], lane & ~3);

        const float sgn = (den >= 0.0f) ? 1.0f : -1.0f;
        den = sgn * fmaxf(fabsf(den), 1e-10f);
        const float inv = 1.0f / den;

        float vn2 = 0.0f;
        #pragma unroll
        for (int c = 0; c < 8; ++c) { v[c] *= inv; vn2 += v[c] * v[c]; }
        vn2 += __shfl_xor_sync(0xffffffffu, vn2, 1);
        vn2 += __shfl_xor_sync(0xffffffffu, vn2, 2);

        const float vn = fmaxf(sqrtf(vn2), 1e-15f);
        const float t1 = tanhf(0.5f * artanh_clip(vn));
        const float rn = fmaxf(t1, 1e-15f);
        const float t2 = tanhf(alpha * artanh_clip(rn));
        const float xs = (t1 / vn) * (t2 / rn);
        const float xn = fmaxf(xs * vn, 1e-15f);
        const float k3 = artanh_clip(xn) / xn;
        const float us = xs * k3;

        float un2 = 0.0f;
        float u[8];
        #pragma unroll
        for (int c = 0; c < 8; ++c) { u[c] = fmaxf(v[c] * us, 0.0f); un2 += u[c] * u[c]; }
        un2 += __shfl_xor_sync(0xffffffffu, un2, 1);
        un2 += __shfl_xor_sync(0xffffffffu, un2, 2);

        const float un = fmaxf(sqrtf(un2), 1e-15f);
        const float k4 = tanhf(un) / un;

        const int row = row_base + wid * 16 + h * 8 + (lane >> 2);
        float* op = out + (size_t)row * D_OUT + 2 * (lane & 3);
        #pragma unroll
        for (int nt = 0; nt < 4; ++nt)
            *reinterpret_cast<float2*>(op + nt * 8) =
                make_float2(u[2 * nt] * k4, u[2 * nt + 1] * k4);
    }
}

// ---------------- host ----------------
typedef CUresult (CUDAAPI *PFN_cuTensorMapEncodeTiled_t)(
    CUtensorMap*, CUtensorMapDataType, cuuint32_t, void*,
    const cuuint64_t*, const cuuint64_t*, const cuuint32_t*, const cuuint32_t*,
    CUtensorMapInterleave, CUtensorMapSwizzle, CUtensorMapL2promotion, CUtensorMapFloatOOBfill);

extern "C" void kernel_launch(void* const* d_in, const int* in_sizes, int n_in,
                              void* d_out, int out_size) {
    const float* X = nullptr; const float* A = nullptr; const float* W = nullptr;
    for (int i = 0; i < n_in; ++i) {
        if (in_sizes[i] == N_ROWS * D_IN)     X = (const float*)d_in[i];
        else if (in_sizes[i] == D_IN * D_OUT) W = (const float*)d_in[i];
        else                                  A = (const float*)d_in[i];   // 16384^2
    }
    float* out = (float*)d_out;

    void* b_ptr = nullptr;
    cudaGetSymbolAddress(&b_ptr, g_Bpk);

    PFN_cuTensorMapEncodeTiled_t encode = nullptr;
    cudaDriverEntryPointQueryResult qr;
    cudaGetDriverEntryPointByVersion("cuTensorMapEncodeTiled", (void**)&encode,
                                     12000, cudaEnableDefault, &qr);

    CUtensorMap tmA;
    {   // A: [16384 x 16384] fp32, box [K=32, M=64], SW128
        cuuint64_t dims[2]    = {N_ROWS, N_ROWS};
        cuuint64_t strides[1] = {(cuuint64_t)N_ROWS * 4};
        cuuint32_t box[2]     = {TK, TM};
        cuuint32_t estr[2]    = {1, 1};
        encode(&tmA, CU_TENSOR_MAP_DATA_TYPE_FLOAT32, 2, (void*)A,
               dims, strides, box, estr,
               CU_TENSOR_MAP_INTERLEAVE_NONE, CU_TENSOR_MAP_SWIZZLE_128B,
               CU_TENSOR_MAP_L2_PROMOTION_L2_128B, CU_TENSOR_MAP_FLOAT_OOB_FILL_NONE);
    }

    prep_kernel<<<N_ROWS / 32, 1024>>>(X, W);

    cudaFuncSetAttribute(gemm_kernel, cudaFuncAttributeMaxDynamicSharedMemorySize, SMEM_DYN);
    gemm_kernel<<<GRID, NTHREADS, SMEM_DYN>>>(tmA, (const float*)b_ptr, out);
}

// round 12
// speedup vs baseline: 3.4608x; 1.2103x over previous
#include <cuda_runtime.h>
#include <cuda.h>
#include <cstdint>

// ---------------- problem constants ----------------
#define N_ROWS  16384
#define D_IN    64
#define D_OUT   32
#define TM      64               // rows per CTA (2 CTAs/SM, grid 256)
#define TK      32               // K per pipeline stage
#define STAGES  6
#define K_ITERS (N_ROWS / TK)    // 512

#define STAGE_A_BYTES (TM * TK * 4)          // 8192
#define STAGE_B_BYTES (2 * 32 * 20 * 4)      // 5120  ([khalf][lane][20 floats])
#define STAGE_BYTES   (STAGE_A_BYTES + STAGE_B_BYTES)   // 13312 (13*1024)
#define SMEM_DYN      (STAGES * STAGE_BYTES + 1024)     // 80896

#define NWARPS_C 4               // consumer warps: w = (mhalf<<1)|khalf
#define NTHREADS (32 * (NWARPS_C + 1))
#define GRID     (N_ROWS / TM)   // 256

// B operand, fragment-packed for M*K-hybrid split:
//   float index = kiter*1280 + khalf*640 + lane*20 + j   (j in 0..19)
//   j = (kp*5 + nt)*2 + h -> B[k = khalf*16 + kp*8 + h*4 + (lane&3)][n = nt*8 + (lane>>2)]
// 512 * 1280 floats = 2.62 MB (L2-resident). Zero-init covers n=34..39 pad.
__device__ float g_Bpk[K_ITERS * 1280];

// ---------------- device helpers ----------------
__device__ __forceinline__ uint32_t smem_u32(const void* p) {
    uint32_t a;
    asm("{ .reg .u64 t; cvta.to.shared.u64 t, %1; cvt.u32.u64 %0, t; }" : "=r"(a) : "l"(p));
    return a;
}
__device__ __forceinline__ float warp_sum(float v) {
    #pragma unroll
    for (int m = 16; m > 0; m >>= 1) v += __shfl_xor_sync(0xffffffffu, v, m);
    return v;
}
__device__ __forceinline__ float artanh_clip(float x) {
    x = fminf(fmaxf(x, -1.0f + 1e-7f), 1.0f - 1e-7f);
    return atanhf(x);
}
__device__ __forceinline__ float tf32_round(float x) {
    uint32_t u;
    asm("cvt.rna.tf32.f32 %0, %1;" : "=r"(u) : "f"(x));
    return __uint_as_float(u);
}
__device__ __forceinline__ uint32_t tf32_bits(float x) {
    uint32_t u;
    asm("cvt.rna.tf32.f32 %0, %1;" : "=r"(u) : "f"(x));
    return u;
}
__device__ __forceinline__ void mbar_init(uint32_t mbar, uint32_t cnt) {
    asm volatile("mbarrier.init.shared.b64 [%0], %1;" :: "r"(mbar), "r"(cnt) : "memory");
}
__device__ __forceinline__ void mbar_expect_tx(uint32_t mbar, uint32_t bytes) {
    asm volatile("mbarrier.arrive.expect_tx.shared.b64 _, [%0], %1;" :: "r"(mbar), "r"(bytes) : "memory");
}
__device__ __forceinline__ void mbar_arrive(uint32_t mbar) {
    asm volatile("mbarrier.arrive.shared.b64 _, [%0];" :: "r"(mbar) : "memory");
}
__device__ __forceinline__ void mbar_wait(uint32_t mbar, uint32_t parity) {
    asm volatile(
        "{\n\t.reg .pred P;\n\t"
        "WL_%=:\n\t"
        "mbarrier.try_wait.parity.shared.b64 P, [%0], %1;\n\t"
        "@!P bra WL_%=;\n\t"
        "}" :: "r"(mbar), "r"(parity) : "memory");
}
__device__ __forceinline__ void tma_load_2d(uint32_t smem_dst, const void* tmap,
                                            int32_t cx, int32_t cy, uint32_t mbar) {
    asm volatile(
        "cp.async.bulk.tensor.2d.shared::cta.global.tile.mbarrier::complete_tx::bytes "
        "[%0], [%1, {%2, %3}], [%4];"
        :: "r"(smem_dst), "l"(tmap), "r"(cx), "r"(cy), "r"(mbar) : "memory");
}
__device__ __forceinline__ void bulk_load(uint32_t smem_dst, const void* gsrc,
                                          uint32_t bytes, uint32_t mbar) {
    asm volatile(
        "cp.async.bulk.shared::cta.global.mbarrier::complete_tx::bytes [%0], [%1], %2, [%3];"
        :: "r"(smem_dst), "l"(gsrc), "r"(bytes), "r"(mbar) : "memory");
}
__device__ __forceinline__ float lds32(uint32_t a) {
    float v;
    asm volatile("ld.shared.f32 %0, [%1];" : "=f"(v) : "r"(a));
    return v;
}
__device__ __forceinline__ void lds128(uint32_t a, uint32_t r[4]) {
    asm volatile("ld.shared.v4.u32 {%0,%1,%2,%3}, [%4];"
                 : "=r"(r[0]), "=r"(r[1]), "=r"(r[2]), "=r"(r[3]) : "r"(a));
}
__device__ __forceinline__ void lds128f(uint32_t a, float r[4]) {
    asm volatile("ld.shared.v4.f32 {%0,%1,%2,%3}, [%4];"
                 : "=f"(r[0]), "=f"(r[1]), "=f"(r[2]), "=f"(r[3]) : "r"(a));
}
__device__ __forceinline__ void sts128f(uint32_t a, const float r[4]) {
    asm volatile("st.shared.v4.f32 [%0], {%1,%2,%3,%4};"
                 :: "r"(a), "f"(r[0]), "f"(r[1]), "f"(r[2]), "f"(r[3]) : "memory");
}
__device__ __forceinline__ void mma_tf32(float c[4], uint32_t a0, uint32_t a1, uint32_t a2, uint32_t a3,
                                         uint32_t b0, uint32_t b1) {
    asm volatile(
        "mma.sync.aligned.m16n8k8.row.col.f32.tf32.tf32.f32 "
        "{%0,%1,%2,%3}, {%4,%5,%6,%7}, {%8,%9}, {%0,%1,%2,%3};"
        : "+f"(c[0]), "+f"(c[1]), "+f"(c[2]), "+f"(c[3])
        : "r"(a0), "r"(a1), "r"(a2), "r"(a3), "r"(b0), "r"(b1));
}

// ---------------- kernel 1: build fragment-packed B (hybrid-split layout) ----------------
__global__ __launch_bounds__(1024) void prep_kernel(const float* __restrict__ X,
                                                    const float* __restrict__ W) {
    __shared__ float Ws[D_IN * D_OUT];
    const int tid = threadIdx.x;
    for (int t = tid; t < D_IN * D_OUT; t += 1024) Ws[t] = W[t];
    __syncthreads();

    const int w = tid >> 5, lane = tid & 31;
    const int i = blockIdx.x * 32 + w;           // global row (= K index of B)

    const float x0 = X[i * D_IN + lane];
    const float x1 = X[i * D_IN + 32 + lane];
    const float xn = fmaxf(sqrtf(warp_sum(x0 * x0 + x1 * x1)), 1e-15f);

    float mx = 0.0f;
    #pragma unroll
    for (int k = 0; k < 32; ++k) mx = fmaf(__shfl_sync(0xffffffffu, x0, k), Ws[k * 32 + lane], mx);
    #pragma unroll
    for (int k = 0; k < 32; ++k) mx = fmaf(__shfl_sync(0xffffffffu, x1, k), Ws[(k + 32) * 32 + lane], mx);

    const float mxn = fmaxf(sqrtf(warp_sum(mx * mx)), 1e-15f);
    const float t   = tanhf((mxn / xn) * artanh_clip(xn));
    const float xw  = t * (mx / mxn);
    const float x2  = warp_sum(xw * xw);
    const float gamma = 2.0f / fmaxf(1.0f - x2, 1e-15f);

    // scatter into hybrid-split fragment layout
    const int k_in  = i & 31;
    const int kiter = i >> 5;
    const int ks    = k_in >> 3;
    const int khalf = ks >> 1;
    const int kp    = ks & 1;
    const int h     = (k_in >> 2) & 1;
    const int il    = k_in & 3;
    float* base = g_Bpk + (size_t)kiter * 1280 + khalf * 640;

    {   // n = lane (0..31): value xw*gamma
        const int nt = lane >> 3;
        const int tl = il | ((lane & 7) << 2);
        const int j  = (kp * 5 + nt) * 2 + h;
        base[tl * 20 + j] = tf32_round(xw * gamma);
    }
    if (lane < 2) {  // n = 32 (gamma-1), n = 33 (1.0); n=34..39 stay zero
        const float e = (lane == 0) ? (gamma - 1.0f) : 1.0f;
        const int tl = il | (lane << 2);
        const int j  = (kp * 5 + 4) * 2 + h;
        base[tl * 20 + j] = tf32_round(e);
    }
}

// ---------------- kernel 2: A @ Y, hybrid M*K-split consumers ----------------
__global__ __launch_bounds__(NTHREADS, 2) void gemm_kernel(
    const __grid_constant__ CUtensorMap tmA,
    const float* __restrict__ Bpk,
    float* __restrict__ out)
{
    extern __shared__ uint8_t smem_dyn[];
    __shared__ __align__(8) uint64_t full_b[STAGES];
    __shared__ __align__(8) uint64_t empty_b[STAGES];

    const int tid  = threadIdx.x;
    const int wid  = tid >> 5;
    const int lane = tid & 31;

    const uint32_t dyn_base = (smem_u32(smem_dyn) + 1023u) & ~1023u;
    const uint32_t full0  = smem_u32(&full_b[0]);
    const uint32_t empty0 = smem_u32(&empty_b[0]);

    if (tid == 0) {
        for (int s = 0; s < STAGES; ++s) {
            mbar_init(full0 + 8u * s, 1);
            mbar_init(empty0 + 8u * s, NWARPS_C);
        }
    }
    __syncthreads();

    const int row_base = blockIdx.x * TM;

    if (wid == NWARPS_C) {
        // -------- producer --------
        if (lane == 0) {
            uint32_t phase = 1;   // fresh-barrier trick: first empty-wait passes
            int s = 0;
            for (int it = 0; it < K_ITERS; ++it) {
                mbar_wait(empty0 + 8u * s, phase);
                const uint32_t fb = full0 + 8u * s;
                mbar_expect_tx(fb, STAGE_BYTES);
                const uint32_t a_dst = dyn_base + (uint32_t)s * STAGE_BYTES;
                tma_load_2d(a_dst, &tmA, it * TK, row_base, fb);    // A box [32 x 64] SW128
                bulk_load(a_dst + STAGE_A_BYTES,
                          Bpk + (size_t)it * 1280, STAGE_B_BYTES, fb);
                if (++s == STAGES) { s = 0; phase ^= 1; }
            }
        }
        return;
    }

    // -------- consumers: warp w = (mhalf<<1)|khalf owns rows mhalf*32..+31, k-half khalf --------
    const uint32_t khalf = (uint32_t)wid & 1u;
    const uint32_t mhalf = (uint32_t)wid >> 1;

    float acc[2][5][4];   // [mt][nt][frag], mt: 16-row tiles within the 32-row half
    #pragma unroll
    for (int mt = 0; mt < 2; ++mt)
        #pragma unroll
        for (int nt = 0; nt < 5; ++nt)
            #pragma unroll
            for (int q = 0; q < 4; ++q) acc[mt][nt][q] = 0.0f;

    const uint32_t lane2 = lane & 3u, lane4 = lane >> 2;
    const uint32_t sw    = lane4 << 4;                            // SW128 XOR (row&7 == lane4)
    const uint32_t cb0   = khalf * 64u + lane2 * 4u;              // kp=0 byte col
    const uint32_t aoff  = (mhalf * 32u + lane4) * 128u;
    const uint32_t boff  = STAGE_A_BYTES + khalf * 2560u + lane * 80u;

    uint32_t phase = 0;
    int s = 0;
    for (int it = 0; it < K_ITERS; ++it) {
        mbar_wait(full0 + 8u * s, phase);
        const uint32_t Abase = dyn_base + (uint32_t)s * STAGE_BYTES;

        // ---- B: 5x LDS.128 (80B lane stride -> phase-conflict-free) ----
        uint32_t br[20];
        {
            const uint32_t bb = Abase + boff;
            lds128(bb,        &br[0]);
            lds128(bb + 16u,  &br[4]);
            lds128(bb + 32u,  &br[8]);
            lds128(bb + 48u,  &br[12]);
            lds128(bb + 64u,  &br[16]);
        }
        // ---- A: 16 scalar LDS (2 mt x 2 kp x 4 frags), then cvt ----
        float afl[2][2][4];
        #pragma unroll
        for (int mt = 0; mt < 2; ++mt) {
            const uint32_t r0 = Abase + aoff + (uint32_t)mt * 2048u;
            #pragma unroll
            for (int kp = 0; kp < 2; ++kp) {
                const uint32_t c0 = cb0 + (uint32_t)kp * 32u;
                afl[mt][kp][0] = lds32(r0 +          (c0 ^ sw));
                afl[mt][kp][1] = lds32(r0 + 1024u +  (c0 ^ sw));
                afl[mt][kp][2] = lds32(r0 +         ((c0 + 16u) ^ sw));
                afl[mt][kp][3] = lds32(r0 + 1024u + ((c0 + 16u) ^ sw));
            }
        }
        uint32_t au[2][2][4];
        #pragma unroll
        for (int mt = 0; mt < 2; ++mt)
            #pragma unroll
            for (int kp = 0; kp < 2; ++kp)
                #pragma unroll
                for (int q = 0; q < 4; ++q) au[mt][kp][q] = tf32_bits(afl[mt][kp][q]);

        if (lane == 0) mbar_arrive(empty0 + 8u * s);   // regs hold everything

        #pragma unroll
        for (int kp = 0; kp < 2; ++kp)
            #pragma unroll
            for (int mt = 0; mt < 2; ++mt)
                #pragma unroll
                for (int nt = 0; nt < 5; ++nt)
                    mma_tf32(acc[mt][nt],
                             au[mt][kp][0], au[mt][kp][1], au[mt][kp][2], au[mt][kp][3],
                             br[(kp * 5 + nt) * 2], br[(kp * 5 + nt) * 2 + 1]);

        if (++s == STAGES) { s = 0; phase ^= 1; }
    }

    // -------- cross-warp k-half reduction via smem (pipeline region reused) --------
    asm volatile("bar.sync 1, 128;" ::: "memory");   // all consumers past final stage reads
    {
        const uint32_t woff = dyn_base + (uint32_t)wid * 5120u + lane * 16u;
        #pragma unroll
        for (int mt = 0; mt < 2; ++mt)
            #pragma unroll
            for (int nt = 0; nt < 5; ++nt)
                sts128f(woff + (uint32_t)(mt * 5 + nt) * 512u, acc[mt][nt]);
    }
    asm volatile("bar.sync 1, 128;" ::: "memory");

    // warp w processes m-tile msel = wid&1 of its m-half; reads own + k-partner sums from smem
    const uint32_t msel  = (uint32_t)wid & 1u;       // which mt this warp finishes
    const uint32_t partner = (uint32_t)wid ^ 1u;     // same mhalf, other khalf
    float vsum[5][4];
    {
        const uint32_t own  = dyn_base + (uint32_t)wid    * 5120u + msel * 2560u + lane * 16u;
        const uint32_t oth  = dyn_base + (uint32_t)partner * 5120u + msel * 2560u + lane * 16u;
        #pragma unroll
        for (int nt = 0; nt < 5; ++nt) {
            float t0[4], t1[4];
            lds128f(own + (uint32_t)nt * 512u, t0);
            lds128f(oth + (uint32_t)nt * 512u, t1);
            #pragma unroll
            for (int q = 0; q < 4; ++q) vsum[nt][q] = t0[q] + t1[q];
        }
    }

    // -------- epilogue: hyperbolic chain per row-half --------
    #pragma unroll
    for (int h = 0; h < 2; ++h) {
        float v[8];
        #pragma unroll
        for (int nt = 0; nt < 4; ++nt) {
            v[2 * nt]     = vsum[nt][2 * h];
            v[2 * nt + 1] = vsum[nt][2 * h + 1];
        }
        float den   = __shfl_sync(0xffffffffu, vsum[4][2 * h],     lane & ~3);
        float alpha = __shfl_sync(0xffffffffu, vsum[4][2 * h + 1], lane & ~3);

        const float sgn = (den >= 0.0f) ? 1.0f : -1.0f;
        den = sgn * fmaxf(fabsf(den), 1e-10f);
        const float inv = 1.0f / den;

        float vn2 = 0.0f;
        #pragma unroll
        for (int c = 0; c < 8; ++c) { v[c] *= inv; vn2 += v[c] * v[c]; }
        vn2 += __shfl_xor_sync(0xffffffffu, vn2, 1);
        vn2 += __shfl_xor_sync(0xffffffffu, vn2, 2);

        const float vn = fmaxf(sqrtf(vn2), 1e-15f);
        const float t1 = tanhf(0.5f * artanh_clip(vn));
        const float rn = fmaxf(t1, 1e-15f);
        const float t2 = tanhf(alpha * artanh_clip(rn));
        const float xs = (t1 / vn) * (t2 / rn);
        const float xn = fmaxf(xs * vn, 1e-15f);
        const float k3 = artanh_clip(xn) / xn;
        const float us = xs * k3;

        float un2 = 0.0f;
        float u[8];
        #pragma unroll
        for (int c = 0; c < 8; ++c) { u[c] = fmaxf(v[c] * us, 0.0f); un2 += u[c] * u[c]; }
        un2 += __shfl_xor_sync(0xffffffffu, un2, 1);
        un2 += __shfl_xor_sync(0xffffffffu, un2, 2);

        const float un = fmaxf(sqrtf(un2), 1e-15f);
        const float k4 = tanhf(un) / un;

        const int row = row_base + (int)(mhalf * 32u + msel * 16u) + h * 8 + (lane >> 2);
        float* op = out + (size_t)row * D_OUT + 2 * (lane & 3);
        #pragma unroll
        for (int nt = 0; nt < 4; ++nt)
            *reinterpret_cast<float2*>(op + nt * 8) =
                make_float2(u[2 * nt] * k4, u[2 * nt + 1] * k4);
    }
}

// ---------------- host ----------------
typedef CUresult (CUDAAPI *PFN_cuTensorMapEncodeTiled_t)(
    CUtensorMap*, CUtensorMapDataType, cuuint32_t, void*,
    const cuuint64_t*, const cuuint64_t*, const cuuint32_t*, const cuuint32_t*,
    CUtensorMapInterleave, CUtensorMapSwizzle, CUtensorMapL2promotion, CUtensorMapFloatOOBfill);

extern "C" void kernel_launch(void* const* d_in, const int* in_sizes, int n_in,
                              void* d_out, int out_size) {
    const float* X = nullptr; const float* A = nullptr; const float* W = nullptr;
    for (int i = 0; i < n_in; ++i) {
        if (in_sizes[i] == N_ROWS * D_IN)     X = (const float*)d_in[i];
        else if (in_sizes[i] == D_IN * D_OUT) W = (const float*)d_in[i];
        else                                  A = (const float*)d_in[i];   // 16384^2
    }
    float* out = (float*)d_out;

    void* b_ptr = nullptr;
    cudaGetSymbolAddress(&b_ptr, g_Bpk);

    PFN_cuTensorMapEncodeTiled_t encode = nullptr;
    cudaDriverEntryPointQueryResult qr;
    cudaGetDriverEntryPointByVersion("cuTensorMapEncodeTiled", (void**)&encode,
                                     12000, cudaEnableDefault, &qr);

    CUtensorMap tmA;
    {   // A: [16384 x 16384] fp32, box [K=32, M=64], SW128
        cuuint64_t dims[2]    = {N_ROWS, N_ROWS};
        cuuint64_t strides[1] = {(cuuint64_t)N_ROWS * 4};
        cuuint32_t box[2]     = {TK, TM};
        cuuint32_t estr[2]    = {1, 1};
        encode(&tmA, CU_TENSOR_MAP_DATA_TYPE_FLOAT32, 2, (void*)A,
               dims, strides, box, estr,
               CU_TENSOR_MAP_INTERLEAVE_NONE, CU_TENSOR_MAP_SWIZZLE_128B,
               CU_TENSOR_MAP_L2_PROMOTION_L2_128B, CU_TENSOR_MAP_FLOAT_OOB_FILL_NONE);
    }

    prep_kernel<<<N_ROWS / 32, 1024>>>(X, W);

    cudaFuncSetAttribute(gemm_kernel, cudaFuncAttributeMaxDynamicSharedMemorySize, SMEM_DYN);
    gemm_kernel<<<GRID, NTHREADS, SMEM_DYN>>>(tmA, (const float*)b_ptr, out);
}

// round 13
// speedup vs baseline: 3.5834x; 1.0354x over previous
#include <cuda_runtime.h>
#include <cuda.h>
#include <cstdint>

// ---------------- problem constants ----------------
#define N_ROWS  16384
#define D_IN    64
#define D_OUT   32
#define TM      64               // rows per CTA (2 CTAs/SM, grid 256)
#define TK      32               // K per pipeline stage
#define STAGES  8
#define K_ITERS (N_ROWS / TK)    // 512

#define STAGE_A_BYTES (TM * TK * 4)          // 8192
#define STAGE_B_BYTES (2 * 32 * 20 * 4)      // 5120  ([khalf][lane][20 floats])
#define STAGE_BYTES   (STAGE_A_BYTES + STAGE_B_BYTES)   // 13312 (13*1024)
#define SMEM_DYN      (STAGES * STAGE_BYTES + 1024)     // 107520 (x2 CTAs = 210KB)

#define NWARPS_C 4               // consumer warps: w = (mhalf<<1)|khalf
#define NTHREADS (32 * (NWARPS_C + 1))
#define GRID     (N_ROWS / TM)   // 256

// B operand, fragment-packed for M*K-hybrid split:
//   float index = kiter*1280 + khalf*640 + lane*20 + j   (j in 0..19)
//   j = (kp*5 + nt)*2 + h -> B[k = khalf*16 + kp*8 + h*4 + (lane&3)][n = nt*8 + (lane>>2)]
// 512 * 1280 floats = 2.62 MB (L2-resident). Zero-init covers n=34..39 pad.
__device__ float g_Bpk[K_ITERS * 1280];

// ---------------- device helpers ----------------
__device__ __forceinline__ uint32_t smem_u32(const void* p) {
    uint32_t a;
    asm("{ .reg .u64 t; cvta.to.shared.u64 t, %1; cvt.u32.u64 %0, t; }" : "=r"(a) : "l"(p));
    return a;
}
__device__ __forceinline__ float warp_sum(float v) {
    #pragma unroll
    for (int m = 16; m > 0; m >>= 1) v += __shfl_xor_sync(0xffffffffu, v, m);
    return v;
}
__device__ __forceinline__ float artanh_clip(float x) {
    x = fminf(fmaxf(x, -1.0f + 1e-7f), 1.0f - 1e-7f);
    return atanhf(x);
}
__device__ __forceinline__ float tf32_round(float x) {
    uint32_t u;
    asm("cvt.rna.tf32.f32 %0, %1;" : "=r"(u) : "f"(x));
    return __uint_as_float(u);
}
__device__ __forceinline__ void mbar_init(uint32_t mbar, uint32_t cnt) {
    asm volatile("mbarrier.init.shared.b64 [%0], %1;" :: "r"(mbar), "r"(cnt) : "memory");
}
__device__ __forceinline__ void mbar_expect_tx(uint32_t mbar, uint32_t bytes) {
    asm volatile("mbarrier.arrive.expect_tx.shared.b64 _, [%0], %1;" :: "r"(mbar), "r"(bytes) : "memory");
}
__device__ __forceinline__ void mbar_arrive(uint32_t mbar) {
    asm volatile("mbarrier.arrive.shared.b64 _, [%0];" :: "r"(mbar) : "memory");
}
__device__ __forceinline__ void mbar_wait(uint32_t mbar, uint32_t parity) {
    asm volatile(
        "{\n\t.reg .pred P;\n\t"
        "WL_%=:\n\t"
        "mbarrier.try_wait.parity.shared.b64 P, [%0], %1;\n\t"
        "@!P bra WL_%=;\n\t"
        "}" :: "r"(mbar), "r"(parity) : "memory");
}
__device__ __forceinline__ void tma_load_2d(uint32_t smem_dst, const void* tmap,
                                            int32_t cx, int32_t cy, uint32_t mbar) {
    asm volatile(
        "cp.async.bulk.tensor.2d.shared::cta.global.tile.mbarrier::complete_tx::bytes "
        "[%0], [%1, {%2, %3}], [%4];"
        :: "r"(smem_dst), "l"(tmap), "r"(cx), "r"(cy), "r"(mbar) : "memory");
}
__device__ __forceinline__ void bulk_load(uint32_t smem_dst, const void* gsrc,
                                          uint32_t bytes, uint32_t mbar) {
    asm volatile(
        "cp.async.bulk.shared::cta.global.mbarrier::complete_tx::bytes [%0], [%1], %2, [%3];"
        :: "r"(smem_dst), "l"(gsrc), "r"(bytes), "r"(mbar) : "memory");
}
__device__ __forceinline__ float lds32(uint32_t a) {
    float v;
    asm volatile("ld.shared.f32 %0, [%1];" : "=f"(v) : "r"(a));
    return v;
}
__device__ __forceinline__ void lds128(uint32_t a, uint32_t r[4]) {
    asm volatile("ld.shared.v4.u32 {%0,%1,%2,%3}, [%4];"
                 : "=r"(r[0]), "=r"(r[1]), "=r"(r[2]), "=r"(r[3]) : "r"(a));
}
__device__ __forceinline__ void lds128f(uint32_t a, float r[4]) {
    asm volatile("ld.shared.v4.f32 {%0,%1,%2,%3}, [%4];"
                 : "=f"(r[0]), "=f"(r[1]), "=f"(r[2]), "=f"(r[3]) : "r"(a));
}
__device__ __forceinline__ void sts128f(uint32_t a, const float r[4]) {
    asm volatile("st.shared.v4.f32 [%0], {%1,%2,%3,%4};"
                 :: "r"(a), "f"(r[0]), "f"(r[1]), "f"(r[2]), "f"(r[3]) : "memory");
}
__device__ __forceinline__ void mma_tf32(float c[4], uint32_t a0, uint32_t a1, uint32_t a2, uint32_t a3,
                                         uint32_t b0, uint32_t b1) {
    asm volatile(
        "mma.sync.aligned.m16n8k8.row.col.f32.tf32.tf32.f32 "
        "{%0,%1,%2,%3}, {%4,%5,%6,%7}, {%8,%9}, {%0,%1,%2,%3};"
        : "+f"(c[0]), "+f"(c[1]), "+f"(c[2]), "+f"(c[3])
        : "r"(a0), "r"(a1), "r"(a2), "r"(a3), "r"(b0), "r"(b1));
}

// ---------------- kernel 1: build fragment-packed B (hybrid-split layout) ----------------
__global__ __launch_bounds__(1024) void prep_kernel(const float* __restrict__ X,
                                                    const float* __restrict__ W) {
    __shared__ float Ws[D_IN * D_OUT];
    const int tid = threadIdx.x;
    for (int t = tid; t < D_IN * D_OUT; t += 1024) Ws[t] = W[t];
    __syncthreads();

    const int w = tid >> 5, lane = tid & 31;
    const int i = blockIdx.x * 32 + w;           // global row (= K index of B)

    const float x0 = X[i * D_IN + lane];
    const float x1 = X[i * D_IN + 32 + lane];
    const float xn = fmaxf(sqrtf(warp_sum(x0 * x0 + x1 * x1)), 1e-15f);

    float mx = 0.0f;
    #pragma unroll
    for (int k = 0; k < 32; ++k) mx = fmaf(__shfl_sync(0xffffffffu, x0, k), Ws[k * 32 + lane], mx);
    #pragma unroll
    for (int k = 0; k < 32; ++k) mx = fmaf(__shfl_sync(0xffffffffu, x1, k), Ws[(k + 32) * 32 + lane], mx);

    const float mxn = fmaxf(sqrtf(warp_sum(mx * mx)), 1e-15f);
    const float t   = tanhf((mxn / xn) * artanh_clip(xn));
    const float xw  = t * (mx / mxn);
    const float x2  = warp_sum(xw * xw);
    const float gamma = 2.0f / fmaxf(1.0f - x2, 1e-15f);

    // scatter into hybrid-split fragment layout
    const int k_in  = i & 31;
    const int kiter = i >> 5;
    const int ks    = k_in >> 3;
    const int khalf = ks >> 1;
    const int kp    = ks & 1;
    const int h     = (k_in >> 2) & 1;
    const int il    = k_in & 3;
    float* base = g_Bpk + (size_t)kiter * 1280 + khalf * 640;

    {   // n = lane (0..31): value xw*gamma
        const int nt = lane >> 3;
        const int tl = il | ((lane & 7) << 2);
        const int j  = (kp * 5 + nt) * 2 + h;
        base[tl * 20 + j] = tf32_round(xw * gamma);
    }
    if (lane < 2) {  // n = 32 (gamma-1), n = 33 (1.0); n=34..39 stay zero
        const float e = (lane == 0) ? (gamma - 1.0f) : 1.0f;
        const int tl = il | (lane << 2);
        const int j  = (kp * 5 + 4) * 2 + h;
        base[tl * 20 + j] = tf32_round(e);
    }
}

// ---------------- kernel 2: A @ Y, hybrid M*K-split consumers ----------------
__global__ __launch_bounds__(NTHREADS, 2) void gemm_kernel(
    const __grid_constant__ CUtensorMap tmA,
    const float* __restrict__ Bpk,
    float* __restrict__ out)
{
    extern __shared__ uint8_t smem_dyn[];
    __shared__ __align__(8) uint64_t full_b[STAGES];
    __shared__ __align__(8) uint64_t empty_b[STAGES];

    const int tid  = threadIdx.x;
    const int wid  = tid >> 5;
    const int lane = tid & 31;

    const uint32_t dyn_base = (smem_u32(smem_dyn) + 1023u) & ~1023u;
    const uint32_t full0  = smem_u32(&full_b[0]);
    const uint32_t empty0 = smem_u32(&empty_b[0]);

    if (tid == 0) {
        for (int s = 0; s < STAGES; ++s) {
            mbar_init(full0 + 8u * s, 1);
            mbar_init(empty0 + 8u * s, NWARPS_C);
        }
    }
    __syncthreads();

    const int row_base = blockIdx.x * TM;

    if (wid == NWARPS_C) {
        // -------- producer --------
        if (lane == 0) {
            uint32_t phase = 1;   // fresh-barrier trick: first empty-wait passes
            int s = 0;
            for (int it = 0; it < K_ITERS; ++it) {
                mbar_wait(empty0 + 8u * s, phase);
                const uint32_t fb = full0 + 8u * s;
                mbar_expect_tx(fb, STAGE_BYTES);
                const uint32_t a_dst = dyn_base + (uint32_t)s * STAGE_BYTES;
                tma_load_2d(a_dst, &tmA, it * TK, row_base, fb);    // A box [32 x 64] SW128
                bulk_load(a_dst + STAGE_A_BYTES,
                          Bpk + (size_t)it * 1280, STAGE_B_BYTES, fb);
                if (++s == STAGES) { s = 0; phase ^= 1; }
            }
        }
        return;
    }

    // -------- consumers: warp w = (mhalf<<1)|khalf owns rows mhalf*32..+31, k-half khalf --------
    const uint32_t khalf = (uint32_t)wid & 1u;
    const uint32_t mhalf = (uint32_t)wid >> 1;

    float acc[2][5][4];   // [mt][nt][frag], mt: 16-row tiles within the 32-row half
    #pragma unroll
    for (int mt = 0; mt < 2; ++mt)
        #pragma unroll
        for (int nt = 0; nt < 5; ++nt)
            #pragma unroll
            for (int q = 0; q < 4; ++q) acc[mt][nt][q] = 0.0f;

    const uint32_t lane2 = lane & 3u, lane4 = lane >> 2;
    const uint32_t sw    = lane4 << 4;                            // SW128 XOR (row&7 == lane4)
    const uint32_t cb0   = khalf * 64u + lane2 * 4u;              // kp=0 byte col
    const uint32_t aoff  = (mhalf * 32u + lane4) * 128u;
    const uint32_t boff  = STAGE_A_BYTES + khalf * 2560u + lane * 80u;

    uint32_t phase = 0;
    int s = 0;
    for (int it = 0; it < K_ITERS; ++it) {
        mbar_wait(full0 + 8u * s, phase);
        const uint32_t Abase = dyn_base + (uint32_t)s * STAGE_BYTES;

        // ---- B: 5x LDS.128 (80B lane stride -> phase-conflict-free) ----
        uint32_t br[20];
        {
            const uint32_t bb = Abase + boff;
            lds128(bb,        &br[0]);
            lds128(bb + 16u,  &br[4]);
            lds128(bb + 32u,  &br[8]);
            lds128(bb + 48u,  &br[12]);
            lds128(bb + 64u,  &br[16]);
        }
        // ---- A: 16 scalar LDS; raw fp32 bits feed tf32 mma (HW truncation, bias cancels) ----
        uint32_t au[2][2][4];
        #pragma unroll
        for (int mt = 0; mt < 2; ++mt) {
            const uint32_t r0 = Abase + aoff + (uint32_t)mt * 2048u;
            #pragma unroll
            for (int kp = 0; kp < 2; ++kp) {
                const uint32_t c0 = cb0 + (uint32_t)kp * 32u;
                au[mt][kp][0] = __float_as_uint(lds32(r0 +          (c0 ^ sw)));
                au[mt][kp][1] = __float_as_uint(lds32(r0 + 1024u +  (c0 ^ sw)));
                au[mt][kp][2] = __float_as_uint(lds32(r0 +         ((c0 + 16u) ^ sw)));
                au[mt][kp][3] = __float_as_uint(lds32(r0 + 1024u + ((c0 + 16u) ^ sw)));
            }
        }

        if (lane == 0) mbar_arrive(empty0 + 8u * s);   // regs hold everything

        #pragma unroll
        for (int kp = 0; kp < 2; ++kp)
            #pragma unroll
            for (int mt = 0; mt < 2; ++mt)
                #pragma unroll
                for (int nt = 0; nt < 5; ++nt)
                    mma_tf32(acc[mt][nt],
                             au[mt][kp][0], au[mt][kp][1], au[mt][kp][2], au[mt][kp][3],
                             br[(kp * 5 + nt) * 2], br[(kp * 5 + nt) * 2 + 1]);

        if (++s == STAGES) { s = 0; phase ^= 1; }
    }

    // -------- cross-warp k-half reduction via smem (pipeline region reused) --------
    asm volatile("bar.sync 1, 128;" ::: "memory");   // all consumers past final stage reads
    {
        const uint32_t woff = dyn_base + (uint32_t)wid * 5120u + lane * 16u;
        #pragma unroll
        for (int mt = 0; mt < 2; ++mt)
            #pragma unroll
            for (int nt = 0; nt < 5; ++nt)
                sts128f(woff + (uint32_t)(mt * 5 + nt) * 512u, acc[mt][nt]);
    }
    asm volatile("bar.sync 1, 128;" ::: "memory");

    // warp w processes m-tile msel = wid&1 of its m-half; reads own + k-partner sums from smem
    const uint32_t msel  = (uint32_t)wid & 1u;       // which mt this warp finishes
    const uint32_t partner = (uint32_t)wid ^ 1u;     // same mhalf, other khalf
    float vsum[5][4];
    {
        const uint32_t own  = dyn_base + (uint32_t)wid    * 5120u + msel * 2560u + lane * 16u;
        const uint32_t oth  = dyn_base + (uint32_t)partner * 5120u + msel * 2560u + lane * 16u;
        #pragma unroll
        for (int nt = 0; nt < 5; ++nt) {
            float t0[4], t1[4];
            lds128f(own + (uint32_t)nt * 512u, t0);
            lds128f(oth + (uint32_t)nt * 512u, t1);
            #pragma unroll
            for (int q = 0; q < 4; ++q) vsum[nt][q] = t0[q] + t1[q];
        }
    }

    // -------- epilogue: hyperbolic chain per row-half --------
    #pragma unroll
    for (int h = 0; h < 2; ++h) {
        float v[8];
        #pragma unroll
        for (int nt = 0; nt < 4; ++nt) {
            v[2 * nt]     = vsum[nt][2 * h];
            v[2 * nt + 1] = vsum[nt][2 * h + 1];
        }
        float den   = __shfl_sync(0xffffffffu, vsum[4][2 * h],     lane & ~3);
        float alpha = __shfl_sync(0xffffffffu, vsum[4][2 * h + 1], lane & ~3);

        const float sgn = (den >= 0.0f) ? 1.0f : -1.0f;
        den = sgn * fmaxf(fabsf(den), 1e-10f);
        const float inv = 1.0f / den;

        float vn2 = 0.0f;
        #pragma unroll
        for (int c = 0; c < 8; ++c) { v[c] *= inv; vn2 += v[c] * v[c]; }
        vn2 += __shfl_xor_sync(0xffffffffu, vn2, 1);
        vn2 += __shfl_xor_sync(0xffffffffu, vn2, 2);

        const float vn = fmaxf(sqrtf(vn2), 1e-15f);
        const float t1 = tanhf(0.5f * artanh_clip(vn));
        const float rn = fmaxf(t1, 1e-15f);
        const float t2 = tanhf(alpha * artanh_clip(rn));
        const float xs = (t1 / vn) * (t2 / rn);
        const float xn = fmaxf(xs * vn, 1e-15f);
        const float k3 = artanh_clip(xn) / xn;
        const float us = xs * k3;

        float un2 = 0.0f;
        float u[8];
        #pragma unroll
        for (int c = 0; c < 8; ++c) { u[c] = fmaxf(v[c] * us, 0.0f); un2 += u[c] * u[c]; }
        un2 += __shfl_xor_sync(0xffffffffu, un2, 1);
        un2 += __shfl_xor_sync(0xffffffffu, un2, 2);

        const float un = fmaxf(sqrtf(un2), 1e-15f);
        const float k4 = tanhf(un) / un;

        const int row = row_base + (int)(mhalf * 32u + msel * 16u) + h * 8 + (lane >> 2);
        float* op = out + (size_t)row * D_OUT + 2 * (lane & 3);
        #pragma unroll
        for (int nt = 0; nt < 4; ++nt)
            *reinterpret_cast<float2*>(op + nt * 8) =
                make_float2(u[2 * nt] * k4, u[2 * nt + 1] * k4);
    }
}

// ---------------- host ----------------
typedef CUresult (CUDAAPI *PFN_cuTensorMapEncodeTiled_t)(
    CUtensorMap*, CUtensorMapDataType, cuuint32_t, void*,
    const cuuint64_t*, const cuuint64_t*, const cuuint32_t*, const cuuint32_t*,
    CUtensorMapInterleave, CUtensorMapSwizzle, CUtensorMapL2promotion, CUtensorMapFloatOOBfill);

extern "C" void kernel_launch(void* const* d_in, const int* in_sizes, int n_in,
                              void* d_out, int out_size) {
    const float* X = nullptr; const float* A = nullptr; const float* W = nullptr;
    for (int i = 0; i < n_in; ++i) {
        if (in_sizes[i] == N_ROWS * D_IN)     X = (const float*)d_in[i];
        else if (in_sizes[i] == D_IN * D_OUT) W = (const float*)d_in[i];
        else                                  A = (const float*)d_in[i];   // 16384^2
    }
    float* out = (float*)d_out;

    void* b_ptr = nullptr;
    cudaGetSymbolAddress(&b_ptr, g_Bpk);

    PFN_cuTensorMapEncodeTiled_t encode = nullptr;
    cudaDriverEntryPointQueryResult qr;
    cudaGetDriverEntryPointByVersion("cuTensorMapEncodeTiled", (void**)&encode,
                                     12000, cudaEnableDefault, &qr);

    CUtensorMap tmA;
    {   // A: [16384 x 16384] fp32, box [K=32, M=64], SW128
        cuuint64_t dims[2]    = {N_ROWS, N_ROWS};
        cuuint64_t strides[1] = {(cuuint64_t)N_ROWS * 4};
        cuuint32_t box[2]     = {TK, TM};
        cuuint32_t estr[2]    = {1, 1};
        encode(&tmA, CU_TENSOR_MAP_DATA_TYPE_FLOAT32, 2, (void*)A,
               dims, strides, box, estr,
               CU_TENSOR_MAP_INTERLEAVE_NONE, CU_TENSOR_MAP_SWIZZLE_128B,
               CU_TENSOR_MAP_L2_PROMOTION_L2_256B, CU_TENSOR_MAP_FLOAT_OOB_FILL_NONE);
    }

    prep_kernel<<<N_ROWS / 32, 1024>>>(X, W);

    cudaFuncSetAttribute(gemm_kernel, cudaFuncAttributeMaxDynamicSharedMemorySize, SMEM_DYN);
    gemm_kernel<<<GRID, NTHREADS, SMEM_DYN>>>(tmA, (const float*)b_ptr, out);
}